// round 1
// baseline (speedup 1.0000x reference)
#include <cuda_runtime.h>

#define BB 8
#define HH 256
#define WW 256
#define NPIX (BB*HH*WW)
#define N_ITERS 200

// Double-buffered state (alloc-free scratch): 8 x 2MB = 16MB
__device__ float g_u [2][NPIX];
__device__ float g_ub[2][NPIX];
__device__ float g_p [2][NPIX];
__device__ float g_q [2][NPIX];

__global__ void tv_init_kernel(const float* __restrict__ f) {
    int idx = blockIdx.x * blockDim.x + threadIdx.x;
    if (idx < NPIX) {
        float v = f[idx];
        g_u [0][idx] = v;
        g_ub[0][idx] = v;
        g_p [0][idx] = 0.f;
        g_q [0][idx] = 0.f;
    }
}

// One Chambolle-Pock iteration, fused: each thread redundantly computes the
// four dual (p/q) values its own u-update needs, so no intra-iteration
// cross-CTA dependency exists. Reads parity s, writes parity 1-s.
__global__ __launch_bounds__(256) void tv_step_kernel(
    int s,
    const float* __restrict__ f,
    const float* __restrict__ lam)
{
    const float SIG  = 0.35355339f;
    const float TAUc = 0.35355339f;
    const float INV  = 1.0f / (1.0f + TAUc);

    int j = blockIdx.x * 32 + threadIdx.x;
    int i = blockIdx.y * 8  + threadIdx.y;
    int b = blockIdx.z;

    const float* __restrict__ U   = g_u [s];
    const float* __restrict__ UB  = g_ub[s];
    const float* __restrict__ P   = g_p [s];
    const float* __restrict__ Q   = g_q [s];
    float* __restrict__ Un  = g_u [1 - s];
    float* __restrict__ UBn = g_ub[1 - s];
    float* __restrict__ Pn  = g_p [1 - s];
    float* __restrict__ Qn  = g_q [1 - s];

    int idx = (b * HH + i) * WW + j;

    float ubc = UB[idx];

    // p_new(i,j)   : valid i < H-1, lamx(i,j)   = lam(i+1,j)
    // p_new(i-1,j) : valid i > 0,   lamx(i-1,j) = lam(i,j)
    // q_new(i,j)   : valid j < W-1, lamy(i,j)   = lam(i,j+1)
    // q_new(i,j-1) : valid j > 0,   lamy(i,j-1) = lam(i,j)
    float pc = 0.f, pu = 0.f, qc = 0.f, ql = 0.f;

    if (i < HH - 1) {
        float lx = lam[idx + WW];
        float v  = P[idx] + SIG * (UB[idx + WW] - ubc);
        pc = fminf(fmaxf(v, -lx), lx);
    }
    if (i > 0) {
        float lx = lam[idx];
        float v  = P[idx - WW] + SIG * (ubc - UB[idx - WW]);
        pu = fminf(fmaxf(v, -lx), lx);
    }
    if (j < WW - 1) {
        float ly = lam[idx + 1];
        float v  = Q[idx] + SIG * (UB[idx + 1] - ubc);
        qc = fminf(fmaxf(v, -ly), ly);
    }
    if (j > 0) {
        float ly = lam[idx];
        float v  = Q[idx - 1] + SIG * (ubc - UB[idx - 1]);
        ql = fminf(fmaxf(v, -ly), ly);
    }

    // div = dxT(p) + dyT(q) = (p[i-1]-p[i]) + (q[j-1]-q[j])
    float div = (pu - pc) + (ql - qc);

    float uo = U[idx];
    float un = (uo + TAUc * (f[idx] - div)) * INV;

    Un [idx] = un;
    UBn[idx] = 2.f * un - uo;
    if (i < HH - 1) Pn[idx] = pc;
    if (j < WW - 1) Qn[idx] = qc;
}

__global__ void tv_copy_out_kernel(float* __restrict__ out) {
    int idx = blockIdx.x * blockDim.x + threadIdx.x;
    if (idx < NPIX) out[idx] = g_u[0][idx];   // 200 iters -> result parity 0
}

extern "C" void kernel_launch(void* const* d_in, const int* in_sizes, int n_in,
                              void* d_out, int out_size) {
    const float* f   = (const float*)d_in[0];
    const float* lam = (const float*)d_in[1];

    tv_init_kernel<<<(NPIX + 255) / 256, 256>>>(f);

    dim3 blk(32, 8, 1);
    dim3 grd(WW / 32, HH / 8, BB);
    for (int t = 0; t < N_ITERS; t++) {
        tv_step_kernel<<<grd, blk>>>(t & 1, f, lam);
    }

    tv_copy_out_kernel<<<(NPIX + 255) / 256, 256>>>((float*)d_out);
}

// round 2
// speedup vs baseline: 1.6999x; 1.6999x over previous
#include <cuda_runtime.h>
#include <cooperative_groups.h>
namespace cg = cooperative_groups;

#define BB 8
#define HH 256
#define WW 256
#define NPIX (BB*HH*WW)
#define N_ITERS 200
#define TILE_W 64
#define TILE_H 32
#define VPT 8              // rows (pixels) per thread
#define NCTAS 256          // 8 images * (4 x 8) tiles
#define NTHREADS 256       // 64 x 4 threads per tile

// Double-buffered ubar halo exchange buffer (alloc-free scratch, 4MB)
__device__ float g_halo[2][NPIX];

__global__ __launch_bounds__(NTHREADS, 2)
void tv_persist(const float* __restrict__ f,
                const float* __restrict__ lam,
                float* __restrict__ out)
{
    cg::grid_group grid = cg::this_grid();

    const float SIG  = 0.35355339f;
    const float TAUc = 0.35355339f;
    const float INV  = 1.0f / (1.0f + TAUc);

    __shared__ float ubs[TILE_H + 2][TILE_W + 2];

    const int c  = blockIdx.x;
    const int b  = c >> 5;           // image
    const int t  = c & 31;           // tile within image
    const int j0 = (t & 3) * TILE_W;
    const int i0 = (t >> 2) * TILE_H;
    const int tx = threadIdx.x & 63;
    const int ty = threadIdx.x >> 6; // 0..3
    const int j    = j0 + tx;
    const int itop = i0 + ty * VPT;

    const int base = (b * HH + itop) * WW + j;   // pixel k lives at base + k*WW
    const int srow = 1 + ty * VPT;

    // ---- Load all state into registers ----
    float u[VPT], ub[VPT], pc[VPT], qc[VPT], ql[VPT];
    float fv[VPT], lamx[VPT], lamy[VPT], lams[VPT];
#pragma unroll
    for (int k = 0; k < VPT; k++) {
        const int i   = itop + k;
        const int idx = base + k * WW;
        float fk = f[idx];
        u[k] = ub[k] = fv[k] = fk;
        pc[k] = qc[k] = ql[k] = 0.f;
        lamx[k] = (i < HH - 1) ? lam[idx + WW] : 0.f;   // bound for p(i,j)
        lamy[k] = (j < WW - 1) ? lam[idx + 1]  : 0.f;   // bound for q(i,j)
        lams[k] = (j > 0)      ? lam[idx]      : 0.f;   // bound for q(i,j-1)
    }
    float pu_top = 0.f;                                  // p(itop-1, j) state
    const float pu_lam = (itop > 0) ? lam[base] : 0.f;   // its bound = lam(itop,j)

    for (int it = 0; it < N_ITERS; it++) {
        // ---- stage SMEM interior with current ubar ----
#pragma unroll
        for (int k = 0; k < VPT; k++) ubs[srow + k][1 + tx] = ub[k];

        // ---- publish tile-boundary ubar to global halo (parity buffer) ----
        float* H = g_halo[it & 1];
        if (ty == 0) H[base] = ub[0];
        if (ty == 3) H[base + (VPT - 1) * WW] = ub[VPT - 1];
        if (tx == 0 || tx == 63) {
#pragma unroll
            for (int k = 0; k < VPT; k++) H[base + k * WW] = ub[k];
        }

        grid.sync();   // also a block-level barrier: SMEM interior visible

        // ---- pull neighbor halos into SMEM ring ----
        const float* Hc = g_halo[it & 1];
        if (ty == 0)
            ubs[0][1 + tx]          = (i0 > 0)             ? Hc[base - WW]       : 0.f;
        if (ty == 3)
            ubs[TILE_H + 1][1 + tx] = (i0 + TILE_H < HH)   ? Hc[base + VPT * WW] : 0.f;
        if (tx == 0) {
#pragma unroll
            for (int k = 0; k < VPT; k++)
                ubs[srow + k][0]          = (j0 > 0)           ? Hc[base + k * WW - 1] : 0.f;
        }
        if (tx == 63) {
#pragma unroll
            for (int k = 0; k < VPT; k++)
                ubs[srow + k][TILE_W + 1] = (j0 + TILE_W < WW) ? Hc[base + k * WW + 1] : 0.f;
        }
        __syncthreads();

        // ---- one Chambolle-Pock iteration, fully in registers ----
        float ub_above = ubs[srow - 1][1 + tx];
        pu_top = fminf(fmaxf(pu_top + SIG * (ub[0] - ub_above), -pu_lam), pu_lam);
        float pu = pu_top;
#pragma unroll
        for (int k = 0; k < VPT; k++) {
            float ub_below = (k < VPT - 1) ? ub[k + 1] : ubs[srow + VPT][1 + tx];
            float ub_l = ubs[srow + k][tx];
            float ub_r = ubs[srow + k][2 + tx];

            pc[k] = fminf(fmaxf(pc[k] + SIG * (ub_below - ub[k]), -lamx[k]), lamx[k]);
            qc[k] = fminf(fmaxf(qc[k] + SIG * (ub_r    - ub[k]), -lamy[k]), lamy[k]);
            ql[k] = fminf(fmaxf(ql[k] + SIG * (ub[k]   - ub_l ), -lams[k]), lams[k]);

            float div = (pu - pc[k]) + (ql[k] - qc[k]);
            float un  = (u[k] + TAUc * (fv[k] - div)) * INV;
            ub[k] = 2.f * un - u[k];
            u[k]  = un;
            pu    = pc[k];      // p(i,j) becomes next pixel's p(i-1,j)
        }
        __syncthreads();   // protect SMEM WAR before next iteration's writes
    }

#pragma unroll
    for (int k = 0; k < VPT; k++) out[base + k * WW] = u[k];
}

extern "C" void kernel_launch(void* const* d_in, const int* in_sizes, int n_in,
                              void* d_out, int out_size) {
    const float* f   = (const float*)d_in[0];
    const float* lam = (const float*)d_in[1];
    float* out = (float*)d_out;

    void* args[] = { (void*)&f, (void*)&lam, (void*)&out };
    cudaLaunchCooperativeKernel((void*)tv_persist,
                                dim3(NCTAS), dim3(NTHREADS),
                                args, 0, 0);
}